// round 2
// baseline (speedup 1.0000x reference)
#include <cuda_runtime.h>

#define NB 4
#define NC 512
#define ND 64
#define NN 4096

// Scratch (device globals: allocation-free rule)
__device__ float g_f[NB * ND * NN];
__device__ float g_g[NB * ND * NN];
__device__ float g_h[NB * ND * NN];
__device__ float g_o[NB * ND * NN];
__device__ float g_invsig[4];

// exp(x), x <= 0, without MUFU/F2I: magic-constant rounding + degree-5 poly.
// rel err ~2.5e-6. All ops on fixed-latency fma/alu pipes.
__device__ __forceinline__ float fast_exp(float xx) {
    float y = fmaxf(xx * 1.4426950408889634f, -126.0f);  // log2(e), clamp
    float t = y + 12582912.0f;                           // 1.5*2^23 round trick
    int   e = __float_as_int(t) - 0x4b400000;            // integer part k
    float r = t - 12582912.0f;                           // rint(y)
    float f = y - r;                                     // frac in [-0.5, 0.5]
    float p = 1.3333558146e-3f;
    p = fmaf(p, f, 9.6181291076e-3f);
    p = fmaf(p, f, 5.5504108664e-2f);
    p = fmaf(p, f, 2.4022650696e-1f);
    p = fmaf(p, f, 6.9314718056e-1f);
    p = fmaf(p, f, 1.0f);
    return __int_as_float((e + 127) << 23) * p;          // 2^k * 2^f
}

// ---------------------------------------------------------------------------
// Kernel 1: spectral sigma. sigma = ||W @ normalize(W^T u)||; store 1/sigma.
// blockIdx.x = matrix (0:Wf 1:Wg 2:Wh 3:Wv). 512 threads.
// ---------------------------------------------------------------------------
__global__ void sigma_kernel(const float* __restrict__ Wf, const float* __restrict__ Wg,
                             const float* __restrict__ Wh, const float* __restrict__ Wv,
                             const float* __restrict__ uf, const float* __restrict__ ug,
                             const float* __restrict__ uh, const float* __restrict__ uv) {
    __shared__ float sm_u[512];
    __shared__ float sm_v[512];
    __shared__ float sm_red[512];
    const int m = blockIdx.x;
    const int tid = threadIdx.x;
    const float* W;
    const float* u;
    int R, Ccol;
    if (m == 0)      { W = Wf; u = uf; R = 64;  Ccol = 512; }
    else if (m == 1) { W = Wg; u = ug; R = 64;  Ccol = 512; }
    else if (m == 2) { W = Wh; u = uh; R = 64;  Ccol = 512; }
    else             { W = Wv; u = uv; R = 512; Ccol = 64;  }

    if (tid < R) sm_u[tid] = u[tid];
    __syncthreads();

    // t = W^T u  (length Ccol), unnormalized, into sm_v
    if (m < 3) {
        float t = 0.f;
        #pragma unroll 8
        for (int r = 0; r < 64; r++) t += W[r * 512 + tid] * sm_u[r];
        sm_v[tid] = t;
    } else {
        const int c = tid & 63, part = tid >> 6;
        float p = 0.f;
        for (int r = part * 64; r < part * 64 + 64; r++) p += W[r * 64 + c] * sm_u[r];
        sm_red[tid] = p;
        __syncthreads();
        if (tid < 64) {
            float s = 0.f;
            #pragma unroll
            for (int q = 0; q < 8; q++) s += sm_red[q * 64 + tid];
            sm_v[tid] = s;
        }
        __syncthreads();
    }

    // 1/||t||
    float val = (tid < Ccol) ? sm_v[tid] * sm_v[tid] : 0.f;
    sm_red[tid] = val;
    __syncthreads();
    for (int s = 256; s > 0; s >>= 1) {
        if (tid < s) sm_red[tid] += sm_red[tid + s];
        __syncthreads();
    }
    const float inv = rsqrtf(fmaxf(sm_red[0], 1e-24f));
    __syncthreads();

    // sigma^2 = sum_r ((W v_hat)_r)^2
    float partial = 0.f;
    if (m < 3) {
        const int w = tid >> 5, lane = tid & 31;
        float ssq = 0.f;
        #pragma unroll
        for (int rr = 0; rr < 4; rr++) {
            const int r = w * 4 + rr;
            float acc = 0.f;
            for (int c = lane; c < 512; c += 32) acc += W[r * 512 + c] * sm_v[c];
            #pragma unroll
            for (int o = 16; o; o >>= 1) acc += __shfl_xor_sync(0xffffffffu, acc, o);
            acc *= inv;
            ssq += acc * acc;
        }
        partial = (lane == 0) ? ssq : 0.f;
    } else {
        float acc = 0.f;
        #pragma unroll 8
        for (int c = 0; c < 64; c++) acc += W[tid * 64 + c] * sm_v[c];
        acc *= inv;
        partial = acc * acc;
    }
    sm_red[tid] = partial;
    __syncthreads();
    for (int s = 256; s > 0; s >>= 1) {
        if (tid < s) sm_red[tid] += sm_red[tid + s];
        __syncthreads();
    }
    if (tid == 0) g_invsig[m] = rsqrtf(fmaxf(sm_red[0], 1e-24f));
}

// ---------------------------------------------------------------------------
// Kernel 2: QKV projection. f/g/h[b][k][n] = (W x)[k][n]/sigma + bias[k].
// grid (NN/128, 3, NB), 256 threads (16 ty x 16 tx), 4k x 8n per thread.
// dyn smem: x_s[64][128] + W_s[64][68]
// ---------------------------------------------------------------------------
__global__ __launch_bounds__(256) void proj_kernel(
    const float* __restrict__ x,
    const float* __restrict__ Wf, const float* __restrict__ bf,
    const float* __restrict__ Wg, const float* __restrict__ bg,
    const float* __restrict__ Wh, const float* __restrict__ bh) {
    extern __shared__ float sm[];
    float* x_s = sm;             // [64][128]
    float* W_s = sm + 64 * 128;  // [64][68]

    const int m = blockIdx.y;
    const float* W;
    const float* bvec;
    float* outp;
    if (m == 0)      { W = Wf; bvec = bf; outp = g_f; }
    else if (m == 1) { W = Wg; bvec = bg; outp = g_g; }
    else             { W = Wh; bvec = bh; outp = g_h; }

    const int b = blockIdx.z;
    const int n0 = blockIdx.x * 128;
    const int tid = threadIdx.x;
    const int ty = tid >> 4, tx = tid & 15;
    const float inv = g_invsig[m];

    float acc[4][8];
    #pragma unroll
    for (int i = 0; i < 4; i++)
        #pragma unroll
        for (int j = 0; j < 8; j++) acc[i][j] = 0.f;

    for (int c0 = 0; c0 < NC; c0 += 64) {
        __syncthreads();
        #pragma unroll
        for (int it = 0; it < 8; it++) {  // x_s: 2048 float4
            const int i = tid + it * 256;
            const int cc = i >> 5, nn = (i & 31) << 2;
            *(float4*)(x_s + cc * 128 + nn) =
                *(const float4*)(x + (size_t)b * NC * NN + (size_t)(c0 + cc) * NN + n0 + nn);
        }
        #pragma unroll
        for (int it = 0; it < 4; it++) {  // W_s: 1024 float4
            const int i = tid + it * 256;
            const int k = i >> 4, cc = (i & 15) << 2;
            *(float4*)(W_s + k * 68 + cc) = *(const float4*)(W + k * 512 + c0 + cc);
        }
        __syncthreads();

        #pragma unroll 4
        for (int cc = 0; cc < 64; cc++) {
            float wv[4];
            #pragma unroll
            for (int i = 0; i < 4; i++) wv[i] = W_s[(ty * 4 + i) * 68 + cc];
            const float4 xa = *(const float4*)(x_s + cc * 128 + tx * 8);
            const float4 xb = *(const float4*)(x_s + cc * 128 + tx * 8 + 4);
            const float xv[8] = {xa.x, xa.y, xa.z, xa.w, xb.x, xb.y, xb.z, xb.w};
            #pragma unroll
            for (int i = 0; i < 4; i++)
                #pragma unroll
                for (int j = 0; j < 8; j++) acc[i][j] = fmaf(wv[i], xv[j], acc[i][j]);
        }
    }

    #pragma unroll
    for (int i = 0; i < 4; i++) {
        const int k = ty * 4 + i;
        const float bb = bvec[k];
        float4 r1, r2;
        r1.x = fmaf(acc[i][0], inv, bb); r1.y = fmaf(acc[i][1], inv, bb);
        r1.z = fmaf(acc[i][2], inv, bb); r1.w = fmaf(acc[i][3], inv, bb);
        r2.x = fmaf(acc[i][4], inv, bb); r2.y = fmaf(acc[i][5], inv, bb);
        r2.z = fmaf(acc[i][6], inv, bb); r2.w = fmaf(acc[i][7], inv, bb);
        float* dst = outp + (size_t)b * ND * NN + (size_t)k * NN + n0 + tx * 8;
        *(float4*)dst = r1;
        *(float4*)(dst + 4) = r2;
    }
}

// ---------------------------------------------------------------------------
// Kernel 3: flash attention fp32, online softmax.
// grid (NN/128, NB), 256 threads (ty 16 x tx 16).
// S tile 128x128: thread owns rows r=ty*8+i (8), cols c=tx*8+j (8).
// PV: thread owns rows r=ty*8+i (8), dims d=tx*4+j (4).
// dyn smem: qT[64][128] kT[64][128] p_s[128][132] v_s[128][68]
// ---------------------------------------------------------------------------
__global__ __launch_bounds__(256) void attn_kernel() {
    extern __shared__ float sm[];
    float* qT  = sm;                             // [64][128]
    float* kT  = sm + 64 * 128;                  // [64][128]
    float* p_s = sm + 2 * 64 * 128;              // [128][132]
    float* v_s = sm + 2 * 64 * 128 + 128 * 132;  // [128][68] : v_s[col][d]

    const int b = blockIdx.y;
    const int r0 = blockIdx.x * 128;
    const int tid = threadIdx.x;
    const int ty = tid >> 4, tx = tid & 15;

    const float* __restrict__ fq = g_f + (size_t)b * ND * NN;
    const float* __restrict__ gk = g_g + (size_t)b * ND * NN;
    const float* __restrict__ hv = g_h + (size_t)b * ND * NN;

    #pragma unroll
    for (int it = 0; it < 8; it++) {
        const int i = tid + it * 256;
        const int d = i >> 5, rr = (i & 31) << 2;
        *(float4*)(qT + d * 128 + rr) = *(const float4*)(fq + d * NN + r0 + rr);
    }

    float ot[8][4];
    float mreg[8], lreg[8];
    #pragma unroll
    for (int i = 0; i < 8; i++) {
        mreg[i] = -1e30f;
        lreg[i] = 0.f;
        #pragma unroll
        for (int j = 0; j < 4; j++) ot[i][j] = 0.f;
    }

    for (int c0 = 0; c0 < NN; c0 += 128) {
        __syncthreads();  // prev PV done before overwriting kT/v_s/p_s
        #pragma unroll
        for (int it = 0; it < 8; it++) {  // K tile, [d][col]
            const int i = tid + it * 256;
            const int d = i >> 5, cc = (i & 31) << 2;
            *(float4*)(kT + d * 128 + cc) = *(const float4*)(gk + d * NN + c0 + cc);
        }
        #pragma unroll
        for (int it = 0; it < 8; it++) {  // V tile transposed: v_s[col][d]
            const int i = tid + it * 256;
            const int d0 = (i >> 7) << 2, cc = i & 127;
            float4 hh;
            hh.x = hv[(size_t)(d0 + 0) * NN + c0 + cc];
            hh.y = hv[(size_t)(d0 + 1) * NN + c0 + cc];
            hh.z = hv[(size_t)(d0 + 2) * NN + c0 + cc];
            hh.w = hv[(size_t)(d0 + 3) * NN + c0 + cc];
            *(float4*)(v_s + cc * 68 + d0) = hh;
        }
        __syncthreads();

        // S = Q^T K (8x8 per thread)
        float s[8][8];
        #pragma unroll
        for (int i = 0; i < 8; i++)
            #pragma unroll
            for (int j = 0; j < 8; j++) s[i][j] = 0.f;

        #pragma unroll 4
        for (int d = 0; d < 64; d++) {
            const float4 qa = *(const float4*)(qT + d * 128 + ty * 8);
            const float4 qb = *(const float4*)(qT + d * 128 + ty * 8 + 4);
            const float4 ka = *(const float4*)(kT + d * 128 + tx * 8);
            const float4 kb = *(const float4*)(kT + d * 128 + tx * 8 + 4);
            const float qv[8] = {qa.x, qa.y, qa.z, qa.w, qb.x, qb.y, qb.z, qb.w};
            const float kv[8] = {ka.x, ka.y, ka.z, ka.w, kb.x, kb.y, kb.z, kb.w};
            #pragma unroll
            for (int i = 0; i < 8; i++)
                #pragma unroll
                for (int j = 0; j < 8; j++) s[i][j] = fmaf(qv[i], kv[j], s[i][j]);
        }

        // Online softmax per row; row split across the 16 tx lanes.
        #pragma unroll
        for (int i = 0; i < 8; i++) {
            float mloc = s[i][0];
            #pragma unroll
            for (int j = 1; j < 8; j++) mloc = fmaxf(mloc, s[i][j]);
            #pragma unroll
            for (int o = 1; o < 16; o <<= 1)
                mloc = fmaxf(mloc, __shfl_xor_sync(0xffffffffu, mloc, o));
            const float mnew = fmaxf(mreg[i], mloc);
            const float corr = fast_exp(mreg[i] - mnew);
            mreg[i] = mnew;
            float lloc = 0.f;
            #pragma unroll
            for (int j = 0; j < 8; j++) {
                s[i][j] = fast_exp(s[i][j] - mnew);
                lloc += s[i][j];
            }
            #pragma unroll
            for (int o = 1; o < 16; o <<= 1)
                lloc += __shfl_xor_sync(0xffffffffu, lloc, o);
            lreg[i] = lreg[i] * corr + lloc;
            #pragma unroll
            for (int j = 0; j < 4; j++) ot[i][j] *= corr;
            float* prow = p_s + (ty * 8 + i) * 132 + tx * 8;
            *(float4*)prow       = make_float4(s[i][0], s[i][1], s[i][2], s[i][3]);
            *(float4*)(prow + 4) = make_float4(s[i][4], s[i][5], s[i][6], s[i][7]);
        }
        __syncthreads();

        // O += P V   (thread: 8 rows x 4 dims, dims d = tx*4 + j)
        #pragma unroll 2
        for (int cc = 0; cc < 128; cc += 4) {
            float4 vv[4];
            #pragma unroll
            for (int q = 0; q < 4; q++) vv[q] = *(const float4*)(v_s + (cc + q) * 68 + tx * 4);
            #pragma unroll
            for (int i = 0; i < 8; i++) {
                const float4 pa = *(const float4*)(p_s + (ty * 8 + i) * 132 + cc);
                ot[i][0] = fmaf(pa.x, vv[0].x, fmaf(pa.y, vv[1].x, fmaf(pa.z, vv[2].x, fmaf(pa.w, vv[3].x, ot[i][0]))));
                ot[i][1] = fmaf(pa.x, vv[0].y, fmaf(pa.y, vv[1].y, fmaf(pa.z, vv[2].y, fmaf(pa.w, vv[3].y, ot[i][1]))));
                ot[i][2] = fmaf(pa.x, vv[0].z, fmaf(pa.y, vv[1].z, fmaf(pa.z, vv[2].z, fmaf(pa.w, vv[3].z, ot[i][2]))));
                ot[i][3] = fmaf(pa.x, vv[0].w, fmaf(pa.y, vv[1].w, fmaf(pa.z, vv[2].w, fmaf(pa.w, vv[3].w, ot[i][3]))));
            }
        }
    }

    // write o[b][d][n], normalized
    #pragma unroll
    for (int i = 0; i < 8; i++) {
        const float invl = 1.0f / lreg[i];
        const int n = r0 + ty * 8 + i;
        #pragma unroll
        for (int j = 0; j < 4; j++) {
            const int d = tx * 4 + j;
            g_o[(size_t)b * ND * NN + (size_t)d * NN + n] = ot[i][j] * invl;
        }
    }
}

// ---------------------------------------------------------------------------
// Kernel 4: out[b][c][n] = gamma*( (Wv o)/sigma + bv ) + x.
// grid (NN/128, NC/64, NB), 256 threads, thread 4c x 8n.
// dyn smem: o_s[64][128] + W_s[64][68]
// ---------------------------------------------------------------------------
__global__ __launch_bounds__(256) void outproj_kernel(
    const float* __restrict__ x, const float* __restrict__ Wv,
    const float* __restrict__ bv, const float* __restrict__ gamma,
    float* __restrict__ out) {
    extern __shared__ float sm[];
    float* o_s = sm;             // [64 k][128 n]
    float* W_s = sm + 64 * 128;  // [64 c][68]

    const int b = blockIdx.z;
    const int c0 = blockIdx.y * 64;
    const int n0 = blockIdx.x * 128;
    const int tid = threadIdx.x;
    const int ty = tid >> 4, tx = tid & 15;

    #pragma unroll
    for (int it = 0; it < 8; it++) {
        const int i = tid + it * 256;
        const int k = i >> 5, nn = (i & 31) << 2;
        *(float4*)(o_s + k * 128 + nn) =
            *(const float4*)(g_o + (size_t)b * ND * NN + (size_t)k * NN + n0 + nn);
    }
    #pragma unroll
    for (int it = 0; it < 4; it++) {
        const int i = tid + it * 256;
        const int c = i >> 4, kk = (i & 15) << 2;
        *(float4*)(W_s + c * 68 + kk) = *(const float4*)(Wv + (size_t)(c0 + c) * 64 + kk);
    }
    __syncthreads();

    float acc[4][8];
    #pragma unroll
    for (int i = 0; i < 4; i++)
        #pragma unroll
        for (int j = 0; j < 8; j++) acc[i][j] = 0.f;

    #pragma unroll 4
    for (int k = 0; k < 64; k++) {
        float wv[4];
        #pragma unroll
        for (int i = 0; i < 4; i++) wv[i] = W_s[(ty * 4 + i) * 68 + k];
        const float4 oa = *(const float4*)(o_s + k * 128 + tx * 8);
        const float4 ob = *(const float4*)(o_s + k * 128 + tx * 8 + 4);
        const float ov[8] = {oa.x, oa.y, oa.z, oa.w, ob.x, ob.y, ob.z, ob.w};
        #pragma unroll
        for (int i = 0; i < 4; i++)
            #pragma unroll
            for (int j = 0; j < 8; j++) acc[i][j] = fmaf(wv[i], ov[j], acc[i][j]);
    }

    const float inv = g_invsig[3];
    const float gm = gamma[0];
    #pragma unroll
    for (int i = 0; i < 4; i++) {
        const int c = c0 + ty * 4 + i;
        const float bb = bv[c];
        const size_t base = (size_t)b * NC * NN + (size_t)c * NN + n0 + tx * 8;
        const float4 xa = *(const float4*)(x + base);
        const float4 xb = *(const float4*)(x + base + 4);
        float4 r1, r2;
        r1.x = fmaf(gm, fmaf(acc[i][0], inv, bb), xa.x);
        r1.y = fmaf(gm, fmaf(acc[i][1], inv, bb), xa.y);
        r1.z = fmaf(gm, fmaf(acc[i][2], inv, bb), xa.z);
        r1.w = fmaf(gm, fmaf(acc[i][3], inv, bb), xa.w);
        r2.x = fmaf(gm, fmaf(acc[i][4], inv, bb), xb.x);
        r2.y = fmaf(gm, fmaf(acc[i][5], inv, bb), xb.y);
        r2.z = fmaf(gm, fmaf(acc[i][6], inv, bb), xb.z);
        r2.w = fmaf(gm, fmaf(acc[i][7], inv, bb), xb.w);
        *(float4*)(out + base) = r1;
        *(float4*)(out + base + 4) = r2;
    }
}

extern "C" void kernel_launch(void* const* d_in, const int* in_sizes, int n_in,
                              void* d_out, int out_size) {
    const float* x  = (const float*)d_in[0];
    const float* Wf = (const float*)d_in[1];
    const float* bf = (const float*)d_in[2];
    const float* Wg = (const float*)d_in[3];
    const float* bg = (const float*)d_in[4];
    const float* Wh = (const float*)d_in[5];
    const float* bh = (const float*)d_in[6];
    const float* Wv = (const float*)d_in[7];
    const float* bv = (const float*)d_in[8];
    const float* uf = (const float*)d_in[9];
    const float* ug = (const float*)d_in[10];
    const float* uh = (const float*)d_in[11];
    const float* uv = (const float*)d_in[12];
    const float* gamma = (const float*)d_in[13];
    float* out = (float*)d_out;

    const int PROJ_SMEM = (64 * 128 + 64 * 68) * (int)sizeof(float);       // 50176
    const int ATTN_SMEM = (2 * 64 * 128 + 128 * 132 + 128 * 68) * (int)sizeof(float);  // 167936

    cudaFuncSetAttribute(proj_kernel, cudaFuncAttributeMaxDynamicSharedMemorySize, PROJ_SMEM);
    cudaFuncSetAttribute(attn_kernel, cudaFuncAttributeMaxDynamicSharedMemorySize, ATTN_SMEM);
    cudaFuncSetAttribute(outproj_kernel, cudaFuncAttributeMaxDynamicSharedMemorySize, PROJ_SMEM);

    sigma_kernel<<<4, 512>>>(Wf, Wg, Wh, Wv, uf, ug, uh, uv);

    dim3 pg(NN / 128, 3, NB);
    proj_kernel<<<pg, 256, PROJ_SMEM>>>(x, Wf, bf, Wg, bg, Wh, bh);

    dim3 ag(NN / 128, NB);
    attn_kernel<<<ag, 256, ATTN_SMEM>>>();

    dim3 og(NN / 128, NC / 64, NB);
    outproj_kernel<<<og, 256, PROJ_SMEM>>>(x, Wv, bv, gamma, out);
}

// round 9
// speedup vs baseline: 1.8856x; 1.8856x over previous
#include <cuda_runtime.h>
#include <cuda_bf16.h>
#include <cstdint>

#define NB 4
#define NC 512
#define ND 64
#define NN 4096

// ---------------- device scratch (allocation-free rule) ----------------
__device__ float g_o[NB * ND * NN];
__device__ float g_invsig[4];
__device__ __nv_bfloat16 g_fh[NB * NN * ND];  // f [b][n][d] hi
__device__ __nv_bfloat16 g_fl[NB * NN * ND];  // f lo
__device__ __nv_bfloat16 g_gh[NB * NN * ND];  // g [b][n][d] hi
__device__ __nv_bfloat16 g_gl[NB * NN * ND];  // g lo
__device__ __nv_bfloat16 g_hh[NB * ND * NN];  // h [b][d][n] hi
__device__ __nv_bfloat16 g_hl[NB * ND * NN];  // h lo

__device__ __forceinline__ uint32_t smem_to_u32(const void* p) {
    uint32_t a;
    asm("{ .reg .u64 t; cvta.to.shared.u64 t, %1; cvt.u32.u64 %0, t; }" : "=r"(a) : "l"(p));
    return a;
}
__device__ __forceinline__ uint32_t pack_bf16x2(float lo, float hi) {
    uint32_t r;
    asm("cvt.rn.bf16x2.f32 %0, %1, %2;" : "=r"(r) : "f"(hi), "f"(lo));
    return r;
}
__device__ __forceinline__ void ldsm_x4(uint32_t* r, uint32_t addr) {
    asm volatile("ldmatrix.sync.aligned.m8n8.x4.shared.b16 {%0,%1,%2,%3}, [%4];"
                 : "=r"(r[0]), "=r"(r[1]), "=r"(r[2]), "=r"(r[3]) : "r"(addr));
}
__device__ __forceinline__ void mma_bf16(float* c, const uint32_t* a, const uint32_t* b) {
    asm volatile(
        "mma.sync.aligned.m16n8k16.row.col.f32.bf16.bf16.f32 "
        "{%0,%1,%2,%3}, {%4,%5,%6,%7}, {%8,%9}, {%0,%1,%2,%3};"
        : "+f"(c[0]), "+f"(c[1]), "+f"(c[2]), "+f"(c[3])
        : "r"(a[0]), "r"(a[1]), "r"(a[2]), "r"(a[3]), "r"(b[0]), "r"(b[1]));
}

// ---------------------------------------------------------------------------
// Kernel 1: spectral sigma. sigma = ||W @ normalize(W^T u)||; store 1/sigma.
// ---------------------------------------------------------------------------
__global__ void sigma_kernel(const float* __restrict__ Wf, const float* __restrict__ Wg,
                             const float* __restrict__ Wh, const float* __restrict__ Wv,
                             const float* __restrict__ uf, const float* __restrict__ ug,
                             const float* __restrict__ uh, const float* __restrict__ uv) {
    __shared__ float sm_u[512];
    __shared__ float sm_v[512];
    __shared__ float sm_red[512];
    const int m = blockIdx.x;
    const int tid = threadIdx.x;
    const float* W;
    const float* u;
    int R, Ccol;
    if (m == 0)      { W = Wf; u = uf; R = 64;  Ccol = 512; }
    else if (m == 1) { W = Wg; u = ug; R = 64;  Ccol = 512; }
    else if (m == 2) { W = Wh; u = uh; R = 64;  Ccol = 512; }
    else             { W = Wv; u = uv; R = 512; Ccol = 64;  }

    if (tid < R) sm_u[tid] = u[tid];
    __syncthreads();

    if (m < 3) {
        float t = 0.f;
        #pragma unroll 8
        for (int r = 0; r < 64; r++) t += W[r * 512 + tid] * sm_u[r];
        sm_v[tid] = t;
    } else {
        const int c = tid & 63, part = tid >> 6;
        float p = 0.f;
        for (int r = part * 64; r < part * 64 + 64; r++) p += W[r * 64 + c] * sm_u[r];
        sm_red[tid] = p;
        __syncthreads();
        if (tid < 64) {
            float s = 0.f;
            #pragma unroll
            for (int q = 0; q < 8; q++) s += sm_red[q * 64 + tid];
            sm_v[tid] = s;
        }
        __syncthreads();
    }

    float val = (tid < Ccol) ? sm_v[tid] * sm_v[tid] : 0.f;
    sm_red[tid] = val;
    __syncthreads();
    for (int s = 256; s > 0; s >>= 1) {
        if (tid < s) sm_red[tid] += sm_red[tid + s];
        __syncthreads();
    }
    const float inv = rsqrtf(fmaxf(sm_red[0], 1e-24f));
    __syncthreads();

    float partial = 0.f;
    if (m < 3) {
        const int w = tid >> 5, lane = tid & 31;
        float ssq = 0.f;
        #pragma unroll
        for (int rr = 0; rr < 4; rr++) {
            const int r = w * 4 + rr;
            float acc = 0.f;
            for (int c = lane; c < 512; c += 32) acc += W[r * 512 + c] * sm_v[c];
            #pragma unroll
            for (int o = 16; o; o >>= 1) acc += __shfl_xor_sync(0xffffffffu, acc, o);
            acc *= inv;
            ssq += acc * acc;
        }
        partial = (lane == 0) ? ssq : 0.f;
    } else {
        float acc = 0.f;
        #pragma unroll 8
        for (int c = 0; c < 64; c++) acc += W[tid * 64 + c] * sm_v[c];
        acc *= inv;
        partial = acc * acc;
    }
    sm_red[tid] = partial;
    __syncthreads();
    for (int s = 256; s > 0; s >>= 1) {
        if (tid < s) sm_red[tid] += sm_red[tid + s];
        __syncthreads();
    }
    if (tid == 0) g_invsig[m] = rsqrtf(fmaxf(sm_red[0], 1e-24f));
}

// ---------------------------------------------------------------------------
// Kernel 2: QKV projection -> bf16 hi/lo.
// m==0 (f), m==1 (g): [b][n][64].  m==2 (h): [b][64][n].
// ---------------------------------------------------------------------------
__global__ __launch_bounds__(256) void proj_kernel(
    const float* __restrict__ x,
    const float* __restrict__ Wf, const float* __restrict__ bf,
    const float* __restrict__ Wg, const float* __restrict__ bg,
    const float* __restrict__ Wh, const float* __restrict__ bh) {
    extern __shared__ float sm[];
    float* x_s = sm;             // [64][128]
    float* W_s = sm + 64 * 128;  // [64][68]

    const int m = blockIdx.y;
    const float* W;
    const float* bvec;
    if (m == 0)      { W = Wf; bvec = bf; }
    else if (m == 1) { W = Wg; bvec = bg; }
    else             { W = Wh; bvec = bh; }

    const int b = blockIdx.z;
    const int n0 = blockIdx.x * 128;
    const int tid = threadIdx.x;
    const int ty = tid >> 4, tx = tid & 15;
    const float inv = g_invsig[m];

    float acc[4][8];
    #pragma unroll
    for (int i = 0; i < 4; i++)
        #pragma unroll
        for (int j = 0; j < 8; j++) acc[i][j] = 0.f;

    for (int c0 = 0; c0 < NC; c0 += 64) {
        __syncthreads();
        #pragma unroll
        for (int it = 0; it < 8; it++) {
            const int i = tid + it * 256;
            const int cc = i >> 5, nn = (i & 31) << 2;
            *(float4*)(x_s + cc * 128 + nn) =
                *(const float4*)(x + (size_t)b * NC * NN + (size_t)(c0 + cc) * NN + n0 + nn);
        }
        #pragma unroll
        for (int it = 0; it < 4; it++) {
            const int i = tid + it * 256;
            const int k = i >> 4, cc = (i & 15) << 2;
            *(float4*)(W_s + k * 68 + cc) = *(const float4*)(W + k * 512 + c0 + cc);
        }
        __syncthreads();

        #pragma unroll 4
        for (int cc = 0; cc < 64; cc++) {
            float wv[4];
            #pragma unroll
            for (int i = 0; i < 4; i++) wv[i] = W_s[(ty * 4 + i) * 68 + cc];
            const float4 xa = *(const float4*)(x_s + cc * 128 + tx * 8);
            const float4 xb = *(const float4*)(x_s + cc * 128 + tx * 8 + 4);
            const float xv[8] = {xa.x, xa.y, xa.z, xa.w, xb.x, xb.y, xb.z, xb.w};
            #pragma unroll
            for (int i = 0; i < 4; i++)
                #pragma unroll
                for (int j = 0; j < 8; j++) acc[i][j] = fmaf(wv[i], xv[j], acc[i][j]);
        }
    }

    float v[4][8];
    #pragma unroll
    for (int i = 0; i < 4; i++) {
        const float bb = bvec[ty * 4 + i];
        #pragma unroll
        for (int j = 0; j < 8; j++) v[i][j] = fmaf(acc[i][j], inv, bb);
    }

    if (m < 2) {
        __nv_bfloat16* oh = (m == 0) ? g_fh : g_gh;
        __nv_bfloat16* ol = (m == 0) ? g_fl : g_gl;
        #pragma unroll
        for (int j = 0; j < 8; j++) {
            const int n = n0 + tx * 8 + j;
            const size_t base = ((size_t)b * NN + n) * 64 + ty * 4;
            uint32_t h0 = pack_bf16x2(v[0][j], v[1][j]);
            uint32_t h1 = pack_bf16x2(v[2][j], v[3][j]);
            float c0 = __uint_as_float(h0 << 16), c1 = __uint_as_float(h0 & 0xffff0000u);
            float c2 = __uint_as_float(h1 << 16), c3 = __uint_as_float(h1 & 0xffff0000u);
            uint32_t l0 = pack_bf16x2(v[0][j] - c0, v[1][j] - c1);
            uint32_t l1 = pack_bf16x2(v[2][j] - c2, v[3][j] - c3);
            *(uint2*)(oh + base) = make_uint2(h0, h1);
            *(uint2*)(ol + base) = make_uint2(l0, l1);
        }
    } else {
        #pragma unroll
        for (int i = 0; i < 4; i++) {
            const int k = ty * 4 + i;
            const size_t base = ((size_t)b * ND + k) * NN + n0 + tx * 8;
            uint32_t hw[4], lw[4];
            #pragma unroll
            for (int q = 0; q < 4; q++) {
                hw[q] = pack_bf16x2(v[i][2 * q], v[i][2 * q + 1]);
                float c0 = __uint_as_float(hw[q] << 16), c1 = __uint_as_float(hw[q] & 0xffff0000u);
                lw[q] = pack_bf16x2(v[i][2 * q] - c0, v[i][2 * q + 1] - c1);
            }
            *(uint4*)(g_hh + base) = make_uint4(hw[0], hw[1], hw[2], hw[3]);
            *(uint4*)(g_hl + base) = make_uint4(lw[0], lw[1], lw[2], lw[3]);
        }
    }
}

// ---------------------------------------------------------------------------
// Kernel 3: flash attention via mma.sync bf16 hi/lo (3-pass), no-max softmax.
// grid (NN/128, NB), 256 threads = 8 warps; warp w owns q rows w*16..w*16+15.
// smem pitches: Q/K rows 144B (64 bf16 + pad), V rows 272B (128 bf16 + pad).
// ---------------------------------------------------------------------------
#define QH_OFF 0
#define QL_OFF 18432
#define KH_OFF 36864
#define KL_OFF 55296
#define VH_OFF 73728
#define VL_OFF 91136
#define ATTN_SMEM 108544

__global__ __launch_bounds__(256, 1) void attn_kernel() {
    extern __shared__ char smem[];
    const uint32_t sb = smem_to_u32(smem);
    const int b = blockIdx.y;
    const int r0 = blockIdx.x * 128;
    const int tid = threadIdx.x;
    const int w = tid >> 5, lane = tid & 31;

    const __nv_bfloat16* __restrict__ fh = g_fh + (size_t)b * NN * ND;
    const __nv_bfloat16* __restrict__ fl = g_fl + (size_t)b * NN * ND;
    const __nv_bfloat16* __restrict__ gh = g_gh + (size_t)b * NN * ND;
    const __nv_bfloat16* __restrict__ gl = g_gl + (size_t)b * NN * ND;
    const __nv_bfloat16* __restrict__ hh = g_hh + (size_t)b * ND * NN;
    const __nv_bfloat16* __restrict__ hl = g_hl + (size_t)b * ND * NN;

    // Q tiles -> smem
    #pragma unroll
    for (int it = 0; it < 4; it++) {
        const int idx = tid + it * 256;
        const int row = idx >> 3, ch = idx & 7;
        *(uint4*)(smem + QH_OFF + row * 144 + ch * 16) =
            *(const uint4*)(fh + (size_t)(r0 + row) * 64 + ch * 8);
        *(uint4*)(smem + QL_OFF + row * 144 + ch * 16) =
            *(const uint4*)(fl + (size_t)(r0 + row) * 64 + ch * 8);
    }
    __syncthreads();

    // Q A-fragments (m16k16), kept in registers for all 32 tiles
    const int arow = (lane & 7) + ((lane >> 3) & 1) * 8;
    const int acolb = ((lane >> 4) & 1) * 16;
    uint32_t qah[4][4], qal[4][4];
    #pragma unroll
    for (int k = 0; k < 4; k++) {
        ldsm_x4(qah[k], sb + QH_OFF + (w * 16 + arow) * 144 + k * 32 + acolb);
        ldsm_x4(qal[k], sb + QL_OFF + (w * 16 + arow) * 144 + k * 32 + acolb);
    }

    const int brow = (lane & 7) + ((lane >> 4) & 1) * 8;
    const int bcolb = ((lane >> 3) & 1) * 16;

    float Ot[8][4];
    #pragma unroll
    for (int j = 0; j < 8; j++)
        #pragma unroll
        for (int e = 0; e < 4; e++) Ot[j][e] = 0.f;
    float rs0 = 0.f, rs1 = 0.f;

    for (int iter = 0; iter < NN / 128; iter++) {
        const int c0 = iter * 128;
        __syncthreads();
        #pragma unroll
        for (int it = 0; it < 4; it++) {  // K hi/lo: 128 rows x 128B
            const int idx = tid + it * 256;
            const int row = idx >> 3, ch = idx & 7;
            *(uint4*)(smem + KH_OFF + row * 144 + ch * 16) =
                *(const uint4*)(gh + (size_t)(c0 + row) * 64 + ch * 8);
            *(uint4*)(smem + KL_OFF + row * 144 + ch * 16) =
                *(const uint4*)(gl + (size_t)(c0 + row) * 64 + ch * 8);
        }
        #pragma unroll
        for (int it = 0; it < 4; it++) {  // V hi/lo: 64 rows x 256B
            const int idx = tid + it * 256;
            const int row = idx >> 4, ch = idx & 15;
            *(uint4*)(smem + VH_OFF + row * 272 + ch * 16) =
                *(const uint4*)(hh + (size_t)row * NN + c0 + ch * 8);
            *(uint4*)(smem + VL_OFF + row * 272 + ch * 16) =
                *(const uint4*)(hl + (size_t)row * NN + c0 + ch * 8);
        }
        __syncthreads();

        // ---- S = Qh*Kh + Ql*Kh + Qh*Kl ----
        float Cs[16][4];
        #pragma unroll
        for (int j = 0; j < 16; j++)
            #pragma unroll
            for (int e = 0; e < 4; e++) Cs[j][e] = 0.f;

        #pragma unroll
        for (int k = 0; k < 4; k++) {
            #pragma unroll
            for (int h2 = 0; h2 < 2; h2++) {
                uint32_t bfr[8][2];
                #pragma unroll
                for (int jj = 0; jj < 4; jj++) {
                    uint32_t t4[4];
                    ldsm_x4(t4, sb + KH_OFF + ((h2 * 8 + jj * 2) * 8 + brow) * 144 + k * 32 + bcolb);
                    bfr[jj * 2][0] = t4[0]; bfr[jj * 2][1] = t4[1];
                    bfr[jj * 2 + 1][0] = t4[2]; bfr[jj * 2 + 1][1] = t4[3];
                }
                #pragma unroll
                for (int j = 0; j < 8; j++) mma_bf16(Cs[h2 * 8 + j], qah[k], bfr[j]);
                #pragma unroll
                for (int j = 0; j < 8; j++) mma_bf16(Cs[h2 * 8 + j], qal[k], bfr[j]);
                #pragma unroll
                for (int jj = 0; jj < 4; jj++) {
                    uint32_t t4[4];
                    ldsm_x4(t4, sb + KL_OFF + ((h2 * 8 + jj * 2) * 8 + brow) * 144 + k * 32 + bcolb);
                    bfr[jj * 2][0] = t4[0]; bfr[jj * 2][1] = t4[1];
                    bfr[jj * 2 + 1][0] = t4[2]; bfr[jj * 2 + 1][1] = t4[3];
                }
                #pragma unroll
                for (int j = 0; j < 8; j++) mma_bf16(Cs[h2 * 8 + j], qah[k], bfr[j]);
            }
        }

        // ---- softmax (no max; clamp) + row sums ----
        #pragma unroll
        for (int j = 0; j < 16; j++) {
            #pragma unroll
            for (int e = 0; e < 4; e++)
                Cs[j][e] = __expf(fminf(Cs[j][e], 80.f));
            rs0 += Cs[j][0] + Cs[j][1];
            rs1 += Cs[j][2] + Cs[j][3];
        }

        // ---- O += Ph*Vh + Pl*Vh + Ph*Vl  (P converted C-frag -> A-frag in regs) ----
        #pragma unroll
        for (int kk = 0; kk < 8; kk++) {
            uint32_t pah[4], pal[4];
            pah[0] = pack_bf16x2(Cs[2 * kk][0], Cs[2 * kk][1]);
            pah[1] = pack_bf16x2(Cs[2 * kk][2], Cs[2 * kk][3]);
            pah[2] = pack_bf16x2(Cs[2 * kk + 1][0], Cs[2 * kk + 1][1]);
            pah[3] = pack_bf16x2(Cs[2 * kk + 1][2], Cs[2 * kk + 1][3]);
            #pragma unroll
            for (int q = 0; q < 4; q++) {
                const float flo = __uint_as_float(pah[q] << 16);
                const float fhi = __uint_as_float(pah[q] & 0xffff0000u);
                const int jj = 2 * kk + (q >> 1);
                const int e0 = (q & 1) * 2;
                pal[q] = pack_bf16x2(Cs[jj][e0] - flo, Cs[jj][e0 + 1] - fhi);
            }
            uint32_t vb[8][2];
            #pragma unroll
            for (int jj = 0; jj < 4; jj++) {
                uint32_t t4[4];
                ldsm_x4(t4, sb + VH_OFF + (jj * 16 + brow) * 272 + kk * 32 + bcolb);
                vb[jj * 2][0] = t4[0]; vb[jj * 2][1] = t4[1];
                vb[jj * 2 + 1][0] = t4[2]; vb[jj * 2 + 1][1] = t4[3];
            }
            #pragma unroll
            for (int j = 0; j < 8; j++) mma_bf16(Ot[j], pah, vb[j]);
            #pragma unroll
            for (int j = 0; j < 8; j++) mma_bf16(Ot[j], pal, vb[j]);
            #pragma unroll
            for (int jj = 0; jj < 4; jj++) {
                uint32_t t4[4];
                ldsm_x4(t4, sb + VL_OFF + (jj * 16 + brow) * 272 + kk * 32 + bcolb);
                vb[jj * 2][0] = t4[0]; vb[jj * 2][1] = t4[1];
                vb[jj * 2 + 1][0] = t4[2]; vb[jj * 2 + 1][1] = t4[3];
            }
            #pragma unroll
            for (int j = 0; j < 8; j++) mma_bf16(Ot[j], pah, vb[j]);
        }
    }

    // row-sum reduction across the 4 lanes sharing a row
    rs0 += __shfl_xor_sync(0xffffffffu, rs0, 1);
    rs0 += __shfl_xor_sync(0xffffffffu, rs0, 2);
    rs1 += __shfl_xor_sync(0xffffffffu, rs1, 1);
    rs1 += __shfl_xor_sync(0xffffffffu, rs1, 2);
    const float i0 = 1.0f / rs0, i1 = 1.0f / rs1;

    // stage O into smem [64 d][132 n] (reuses K region), then coalesced store
    __syncthreads();
    float* ost = (float*)(smem + KH_OFF);
    {
        const int dq = (lane & 3) * 2;
        const int nq = w * 16 + (lane >> 2);
        #pragma unroll
        for (int j = 0; j < 8; j++) {
            const int d = j * 8 + dq;
            ost[d * 132 + nq]           = Ot[j][0] * i0;
            ost[(d + 1) * 132 + nq]     = Ot[j][1] * i0;
            ost[d * 132 + nq + 8]       = Ot[j][2] * i1;
            ost[(d + 1) * 132 + nq + 8] = Ot[j][3] * i1;
        }
    }
    __syncthreads();
    float* op = g_o + (size_t)b * ND * NN;
    #pragma unroll
    for (int it = 0; it < 8; it++) {
        const int i = tid + it * 256;      // 0..2047
        const int d = i >> 5, nn = (i & 31) * 4;
        *(float4*)(op + (size_t)d * NN + r0 + nn) = *(const float4*)(ost + d * 132 + nn);
    }
}

// ---------------------------------------------------------------------------
// Kernel 4: out[b][c][n] = gamma*( (Wv o)/sigma + bv ) + x.
// ---------------------------------------------------------------------------
__global__ __launch_bounds__(256) void outproj_kernel(
    const float* __restrict__ x, const float* __restrict__ Wv,
    const float* __restrict__ bv, const float* __restrict__ gamma,
    float* __restrict__ out) {
    extern __shared__ float sm[];
    float* o_s = sm;             // [64 k][128 n]
    float* W_s = sm + 64 * 128;  // [64 c][68]

    const int b = blockIdx.z;
    const int c0 = blockIdx.y * 64;
    const int n0 = blockIdx.x * 128;
    const int tid = threadIdx.x;
    const int ty = tid >> 4, tx = tid & 15;

    #pragma unroll
    for (int it = 0; it < 8; it++) {
        const int i = tid + it * 256;
        const int k = i >> 5, nn = (i & 31) << 2;
        *(float4*)(o_s + k * 128 + nn) =
            *(const float4*)(g_o + (size_t)b * ND * NN + (size_t)k * NN + n0 + nn);
    }
    #pragma unroll
    for (int it = 0; it < 4; it++) {
        const int i = tid + it * 256;
        const int c = i >> 4, kk = (i & 15) << 2;
        *(float4*)(W_s + c * 68 + kk) = *(const float4*)(Wv + (size_t)(c0 + c) * 64 + kk);
    }
    __syncthreads();

    float acc[4][8];
    #pragma unroll
    for (int i = 0; i < 4; i++)
        #pragma unroll
        for (int j = 0; j < 8; j++) acc[i][j] = 0.f;

    #pragma unroll 4
    for (int k = 0; k < 64; k++) {
        float wv[4];
        #pragma unroll
        for (int i = 0; i < 4; i++) wv[i] = W_s[(ty * 4 + i) * 68 + k];
        const float4 oa = *(const float4*)(o_s + k * 128 + tx * 8);
        const float4 ob = *(const float4*)(o_s + k * 128 + tx * 8 + 4);
        const float ov[8] = {oa.x, oa.y, oa.z, oa.w, ob.x, ob.y, ob.z, ob.w};
        #pragma unroll
        for (int i = 0; i < 4; i++)
            #pragma unroll
            for (int j = 0; j < 8; j++) acc[i][j] = fmaf(wv[i], ov[j], acc[i][j]);
    }

    const float inv = g_invsig[3];
    const float gm = gamma[0];
    #pragma unroll
    for (int i = 0; i < 4; i++) {
        const int c = c0 + ty * 4 + i;
        const float bb = bv[c];
        const size_t base = (size_t)b * NC * NN + (size_t)c * NN + n0 + tx * 8;
        const float4 xa = *(const float4*)(x + base);
        const float4 xb = *(const float4*)(x + base + 4);
        float4 r1, r2;
        r1.x = fmaf(gm, fmaf(acc[i][0], inv, bb), xa.x);
        r1.y = fmaf(gm, fmaf(acc[i][1], inv, bb), xa.y);
        r1.z = fmaf(gm, fmaf(acc[i][2], inv, bb), xa.z);
        r1.w = fmaf(gm, fmaf(acc[i][3], inv, bb), xa.w);
        r2.x = fmaf(gm, fmaf(acc[i][4], inv, bb), xb.x);
        r2.y = fmaf(gm, fmaf(acc[i][5], inv, bb), xb.y);
        r2.z = fmaf(gm, fmaf(acc[i][6], inv, bb), xb.z);
        r2.w = fmaf(gm, fmaf(acc[i][7], inv, bb), xb.w);
        *(float4*)(out + base) = r1;
        *(float4*)(out + base + 4) = r2;
    }
}

extern "C" void kernel_launch(void* const* d_in, const int* in_sizes, int n_in,
                              void* d_out, int out_size) {
    const float* x  = (const float*)d_in[0];
    const float* Wf = (const float*)d_in[1];
    const float* bf = (const float*)d_in[2];
    const float* Wg = (const float*)d_in[3];
    const float* bg = (const float*)d_in[4];
    const float* Wh = (const float*)d_in[5];
    const float* bh = (const float*)d_in[6];
    const float* Wv = (const float*)d_in[7];
    const float* bv = (const float*)d_in[8];
    const float* uf = (const float*)d_in[9];
    const float* ug = (const float*)d_in[10];
    const float* uh = (const float*)d_in[11];
    const float* uv = (const float*)d_in[12];
    const float* gamma = (const float*)d_in[13];
    float* out = (float*)d_out;

    const int PROJ_SMEM = (64 * 128 + 64 * 68) * (int)sizeof(float);  // 50176

    cudaFuncSetAttribute(proj_kernel, cudaFuncAttributeMaxDynamicSharedMemorySize, PROJ_SMEM);
    cudaFuncSetAttribute(attn_kernel, cudaFuncAttributeMaxDynamicSharedMemorySize, ATTN_SMEM);
    cudaFuncSetAttribute(outproj_kernel, cudaFuncAttributeMaxDynamicSharedMemorySize, PROJ_SMEM);

    sigma_kernel<<<4, 512>>>(Wf, Wg, Wh, Wv, uf, ug, uh, uv);

    dim3 pg(NN / 128, 3, NB);
    proj_kernel<<<pg, 256, PROJ_SMEM>>>(x, Wf, bf, Wg, bg, Wh, bh);

    dim3 ag(NN / 128, NB);
    attn_kernel<<<ag, 256, ATTN_SMEM>>>();

    dim3 og(NN / 128, NC / 64, NB);
    outproj_kernel<<<og, 256, PROJ_SMEM>>>(x, Wv, bv, gamma, out);
}

// round 14
// speedup vs baseline: 2.4318x; 1.2897x over previous
#include <cuda_runtime.h>
#include <cuda_bf16.h>
#include <cstdint>

#define NB 4
#define NC 512
#define ND 64
#define NN 4096

// ---------------- device scratch (allocation-free rule) ----------------
__device__ float g_o[NB * ND * NN];
__device__ float g_invsig[4];
__device__ __nv_bfloat16 g_fh[NB * NN * ND];  // f [b][n][d] hi
__device__ __nv_bfloat16 g_fl[NB * NN * ND];  // f lo
__device__ __nv_bfloat16 g_gh[NB * NN * ND];  // g [b][n][d] hi
__device__ __nv_bfloat16 g_gl[NB * NN * ND];  // g lo
__device__ __nv_bfloat16 g_hh[NB * ND * NN];  // h [b][d][n] (single bf16: PV is 1-pass)

__device__ __forceinline__ uint32_t smem_to_u32(const void* p) {
    uint32_t a;
    asm("{ .reg .u64 t; cvta.to.shared.u64 t, %1; cvt.u32.u64 %0, t; }" : "=r"(a) : "l"(p));
    return a;
}
__device__ __forceinline__ uint32_t pack_bf16x2(float lo, float hi) {
    uint32_t r;
    asm("cvt.rn.bf16x2.f32 %0, %1, %2;" : "=r"(r) : "f"(hi), "f"(lo));
    return r;
}
__device__ __forceinline__ void ldsm_x4(uint32_t* r, uint32_t addr) {
    asm volatile("ldmatrix.sync.aligned.m8n8.x4.shared.b16 {%0,%1,%2,%3}, [%4];"
                 : "=r"(r[0]), "=r"(r[1]), "=r"(r[2]), "=r"(r[3]) : "r"(addr));
}
__device__ __forceinline__ void mma_bf16(float* c, const uint32_t* a, const uint32_t* b) {
    asm volatile(
        "mma.sync.aligned.m16n8k16.row.col.f32.bf16.bf16.f32 "
        "{%0,%1,%2,%3}, {%4,%5,%6,%7}, {%8,%9}, {%0,%1,%2,%3};"
        : "+f"(c[0]), "+f"(c[1]), "+f"(c[2]), "+f"(c[3])
        : "r"(a[0]), "r"(a[1]), "r"(a[2]), "r"(a[3]), "r"(b[0]), "r"(b[1]));
}

// ---------------------------------------------------------------------------
// Kernel 1: spectral sigma. sigma = ||W @ normalize(W^T u)||; store 1/sigma.
// ---------------------------------------------------------------------------
__global__ void sigma_kernel(const float* __restrict__ Wf, const float* __restrict__ Wg,
                             const float* __restrict__ Wh, const float* __restrict__ Wv,
                             const float* __restrict__ uf, const float* __restrict__ ug,
                             const float* __restrict__ uh, const float* __restrict__ uv) {
    __shared__ float sm_u[512];
    __shared__ float sm_v[512];
    __shared__ float sm_red[512];
    const int m = blockIdx.x;
    const int tid = threadIdx.x;
    const float* W;
    const float* u;
    int R, Ccol;
    if (m == 0)      { W = Wf; u = uf; R = 64;  Ccol = 512; }
    else if (m == 1) { W = Wg; u = ug; R = 64;  Ccol = 512; }
    else if (m == 2) { W = Wh; u = uh; R = 64;  Ccol = 512; }
    else             { W = Wv; u = uv; R = 512; Ccol = 64;  }

    if (tid < R) sm_u[tid] = u[tid];
    __syncthreads();

    if (m < 3) {
        float t = 0.f;
        #pragma unroll 8
        for (int r = 0; r < 64; r++) t += W[r * 512 + tid] * sm_u[r];
        sm_v[tid] = t;
    } else {
        const int c = tid & 63, part = tid >> 6;
        float p = 0.f;
        for (int r = part * 64; r < part * 64 + 64; r++) p += W[r * 64 + c] * sm_u[r];
        sm_red[tid] = p;
        __syncthreads();
        if (tid < 64) {
            float s = 0.f;
            #pragma unroll
            for (int q = 0; q < 8; q++) s += sm_red[q * 64 + tid];
            sm_v[tid] = s;
        }
        __syncthreads();
    }

    float val = (tid < Ccol) ? sm_v[tid] * sm_v[tid] : 0.f;
    sm_red[tid] = val;
    __syncthreads();
    for (int s = 256; s > 0; s >>= 1) {
        if (tid < s) sm_red[tid] += sm_red[tid + s];
        __syncthreads();
    }
    const float inv = rsqrtf(fmaxf(sm_red[0], 1e-24f));
    __syncthreads();

    float partial = 0.f;
    if (m < 3) {
        const int w = tid >> 5, lane = tid & 31;
        float ssq = 0.f;
        #pragma unroll
        for (int rr = 0; rr < 4; rr++) {
            const int r = w * 4 + rr;
            float acc = 0.f;
            for (int c = lane; c < 512; c += 32) acc += W[r * 512 + c] * sm_v[c];
            #pragma unroll
            for (int o = 16; o; o >>= 1) acc += __shfl_xor_sync(0xffffffffu, acc, o);
            acc *= inv;
            ssq += acc * acc;
        }
        partial = (lane == 0) ? ssq : 0.f;
    } else {
        float acc = 0.f;
        #pragma unroll 8
        for (int c = 0; c < 64; c++) acc += W[tid * 64 + c] * sm_v[c];
        acc *= inv;
        partial = acc * acc;
    }
    sm_red[tid] = partial;
    __syncthreads();
    for (int s = 256; s > 0; s >>= 1) {
        if (tid < s) sm_red[tid] += sm_red[tid + s];
        __syncthreads();
    }
    if (tid == 0) g_invsig[m] = rsqrtf(fmaxf(sm_red[0], 1e-24f));
}

// ---------------------------------------------------------------------------
// Kernel 2: FUSED QKV projection -> bf16. Loads each x tile ONCE for f,g,h.
// f,g: hi/lo pairs at [b][n][64]. h: single bf16 at [b][64][n].
// grid (NN/128, NB), 256 threads (16x16), per-thread 3 x (4k x 8n).
// dyn smem: x_s[64][128] + W_s[3][64][68]  (84992 B)
// ---------------------------------------------------------------------------
__global__ __launch_bounds__(256) void proj_fused_kernel(
    const float* __restrict__ x,
    const float* __restrict__ Wf, const float* __restrict__ bf,
    const float* __restrict__ Wg, const float* __restrict__ bg,
    const float* __restrict__ Wh, const float* __restrict__ bh) {
    extern __shared__ float sm[];
    float* x_s = sm;             // [64][128]
    float* W_s = sm + 64 * 128;  // [3][64][68]

    const int b = blockIdx.y;
    const int n0 = blockIdx.x * 128;
    const int tid = threadIdx.x;
    const int ty = tid >> 4, tx = tid & 15;
    const float* Wp[3] = {Wf, Wg, Wh};

    float acc[3][4][8];
    #pragma unroll
    for (int m = 0; m < 3; m++)
        #pragma unroll
        for (int i = 0; i < 4; i++)
            #pragma unroll
            for (int j = 0; j < 8; j++) acc[m][i][j] = 0.f;

    for (int c0 = 0; c0 < NC; c0 += 64) {
        __syncthreads();
        #pragma unroll
        for (int it = 0; it < 8; it++) {  // x_s: 2048 float4
            const int i = tid + it * 256;
            const int cc = i >> 5, nn = (i & 31) << 2;
            *(float4*)(x_s + cc * 128 + nn) =
                *(const float4*)(x + (size_t)b * NC * NN + (size_t)(c0 + cc) * NN + n0 + nn);
        }
        #pragma unroll
        for (int it = 0; it < 12; it++) {  // W_s: 3 x 1024 float4
            const int i = tid + it * 256;
            const int m = i >> 10, r = i & 1023;
            const int k = r >> 4, cc = (r & 15) << 2;
            *(float4*)(W_s + m * 64 * 68 + k * 68 + cc) =
                *(const float4*)(Wp[m] + k * 512 + c0 + cc);
        }
        __syncthreads();

        #pragma unroll 2
        for (int cc = 0; cc < 64; cc++) {
            const float4 xa = *(const float4*)(x_s + cc * 128 + tx * 8);
            const float4 xb = *(const float4*)(x_s + cc * 128 + tx * 8 + 4);
            const float xv[8] = {xa.x, xa.y, xa.z, xa.w, xb.x, xb.y, xb.z, xb.w};
            #pragma unroll
            for (int m = 0; m < 3; m++) {
                float wv[4];
                #pragma unroll
                for (int i = 0; i < 4; i++)
                    wv[i] = W_s[m * 64 * 68 + (ty * 4 + i) * 68 + cc];
                #pragma unroll
                for (int i = 0; i < 4; i++)
                    #pragma unroll
                    for (int j = 0; j < 8; j++)
                        acc[m][i][j] = fmaf(wv[i], xv[j], acc[m][i][j]);
            }
        }
    }

    // f, g: hi/lo bf16 at [b][n][64]
    #pragma unroll
    for (int m = 0; m < 2; m++) {
        const float inv = g_invsig[m];
        const float* bvec = (m == 0) ? bf : bg;
        __nv_bfloat16* oh = (m == 0) ? g_fh : g_gh;
        __nv_bfloat16* ol = (m == 0) ? g_fl : g_gl;
        float v[4][8];
        #pragma unroll
        for (int i = 0; i < 4; i++) {
            const float bb = bvec[ty * 4 + i];
            #pragma unroll
            for (int j = 0; j < 8; j++) v[i][j] = fmaf(acc[m][i][j], inv, bb);
        }
        #pragma unroll
        for (int j = 0; j < 8; j++) {
            const int n = n0 + tx * 8 + j;
            const size_t base = ((size_t)b * NN + n) * 64 + ty * 4;
            uint32_t h0 = pack_bf16x2(v[0][j], v[1][j]);
            uint32_t h1 = pack_bf16x2(v[2][j], v[3][j]);
            float c0f = __uint_as_float(h0 << 16), c1f = __uint_as_float(h0 & 0xffff0000u);
            float c2f = __uint_as_float(h1 << 16), c3f = __uint_as_float(h1 & 0xffff0000u);
            uint32_t l0 = pack_bf16x2(v[0][j] - c0f, v[1][j] - c1f);
            uint32_t l1 = pack_bf16x2(v[2][j] - c2f, v[3][j] - c3f);
            *(uint2*)(oh + base) = make_uint2(h0, h1);
            *(uint2*)(ol + base) = make_uint2(l0, l1);
        }
    }
    // h: single bf16 at [b][64][n]
    {
        const float inv = g_invsig[2];
        #pragma unroll
        for (int i = 0; i < 4; i++) {
            const int k = ty * 4 + i;
            const float bb = bh[k];
            const size_t base = ((size_t)b * ND + k) * NN + n0 + tx * 8;
            uint32_t hw[4];
            #pragma unroll
            for (int q = 0; q < 4; q++)
                hw[q] = pack_bf16x2(fmaf(acc[2][i][2 * q], inv, bb),
                                    fmaf(acc[2][i][2 * q + 1], inv, bb));
            *(uint4*)(g_hh + base) = make_uint4(hw[0], hw[1], hw[2], hw[3]);
        }
    }
}

// ---------------------------------------------------------------------------
// Kernel 3: flash attention, mma.sync. S: bf16 hi/lo 3-pass. PV: 1-pass bf16
// (P is positive -> coherent signal, incoherent rounding error ~3e-5).
// grid (NN/128, NB), 256 threads = 8 warps; warp w owns q rows w*16..w*16+15.
// smem pitches: Q/K rows 144B, V rows 272B.
// ---------------------------------------------------------------------------
#define QH_OFF 0
#define QL_OFF 18432
#define KH_OFF 36864
#define KL_OFF 55296
#define VH_OFF 73728
#define ATTN_SMEM 91136

__global__ __launch_bounds__(256, 1) void attn_kernel() {
    extern __shared__ char smem[];
    const uint32_t sb = smem_to_u32(smem);
    const int b = blockIdx.y;
    const int r0 = blockIdx.x * 128;
    const int tid = threadIdx.x;
    const int w = tid >> 5, lane = tid & 31;

    const __nv_bfloat16* __restrict__ fh = g_fh + (size_t)b * NN * ND;
    const __nv_bfloat16* __restrict__ fl = g_fl + (size_t)b * NN * ND;
    const __nv_bfloat16* __restrict__ gh = g_gh + (size_t)b * NN * ND;
    const __nv_bfloat16* __restrict__ gl = g_gl + (size_t)b * NN * ND;
    const __nv_bfloat16* __restrict__ hh = g_hh + (size_t)b * ND * NN;

    // Q tiles -> smem
    #pragma unroll
    for (int it = 0; it < 4; it++) {
        const int idx = tid + it * 256;
        const int row = idx >> 3, ch = idx & 7;
        *(uint4*)(smem + QH_OFF + row * 144 + ch * 16) =
            *(const uint4*)(fh + (size_t)(r0 + row) * 64 + ch * 8);
        *(uint4*)(smem + QL_OFF + row * 144 + ch * 16) =
            *(const uint4*)(fl + (size_t)(r0 + row) * 64 + ch * 8);
    }
    __syncthreads();

    // Q A-fragments (m16k16), kept in registers for all 32 tiles
    const int arow = (lane & 7) + ((lane >> 3) & 1) * 8;
    const int acolb = ((lane >> 4) & 1) * 16;
    uint32_t qah[4][4], qal[4][4];
    #pragma unroll
    for (int k = 0; k < 4; k++) {
        ldsm_x4(qah[k], sb + QH_OFF + (w * 16 + arow) * 144 + k * 32 + acolb);
        ldsm_x4(qal[k], sb + QL_OFF + (w * 16 + arow) * 144 + k * 32 + acolb);
    }

    const int brow = (lane & 7) + ((lane >> 4) & 1) * 8;
    const int bcolb = ((lane >> 3) & 1) * 16;

    float Ot[8][4];
    #pragma unroll
    for (int j = 0; j < 8; j++)
        #pragma unroll
        for (int e = 0; e < 4; e++) Ot[j][e] = 0.f;
    float rs0 = 0.f, rs1 = 0.f;

    for (int iter = 0; iter < NN / 128; iter++) {
        const int c0 = iter * 128;
        __syncthreads();
        #pragma unroll
        for (int it = 0; it < 4; it++) {  // K hi/lo: 128 rows x 128B
            const int idx = tid + it * 256;
            const int row = idx >> 3, ch = idx & 7;
            *(uint4*)(smem + KH_OFF + row * 144 + ch * 16) =
                *(const uint4*)(gh + (size_t)(c0 + row) * 64 + ch * 8);
            *(uint4*)(smem + KL_OFF + row * 144 + ch * 16) =
                *(const uint4*)(gl + (size_t)(c0 + row) * 64 + ch * 8);
        }
        #pragma unroll
        for (int it = 0; it < 4; it++) {  // V: 64 rows x 16 chunks = 1024 uint4
            const int idx = tid + it * 256;
            const int row = idx >> 4, ch = idx & 15;
            *(uint4*)(smem + VH_OFF + row * 272 + ch * 16) =
                *(const uint4*)(hh + (size_t)row * NN + c0 + ch * 8);
        }
        __syncthreads();

        // ---- S = Qh*Kh + Ql*Kh + Qh*Kl ----
        float Cs[16][4];
        #pragma unroll
        for (int j = 0; j < 16; j++)
            #pragma unroll
            for (int e = 0; e < 4; e++) Cs[j][e] = 0.f;

        #pragma unroll
        for (int k = 0; k < 4; k++) {
            #pragma unroll
            for (int h2 = 0; h2 < 2; h2++) {
                uint32_t bfr[8][2];
                #pragma unroll
                for (int jj = 0; jj < 4; jj++) {
                    uint32_t t4[4];
                    ldsm_x4(t4, sb + KH_OFF + ((h2 * 8 + jj * 2) * 8 + brow) * 144 + k * 32 + bcolb);
                    bfr[jj * 2][0] = t4[0]; bfr[jj * 2][1] = t4[1];
                    bfr[jj * 2 + 1][0] = t4[2]; bfr[jj * 2 + 1][1] = t4[3];
                }
                #pragma unroll
                for (int j = 0; j < 8; j++) mma_bf16(Cs[h2 * 8 + j], qah[k], bfr[j]);
                #pragma unroll
                for (int j = 0; j < 8; j++) mma_bf16(Cs[h2 * 8 + j], qal[k], bfr[j]);
                #pragma unroll
                for (int jj = 0; jj < 4; jj++) {
                    uint32_t t4[4];
                    ldsm_x4(t4, sb + KL_OFF + ((h2 * 8 + jj * 2) * 8 + brow) * 144 + k * 32 + bcolb);
                    bfr[jj * 2][0] = t4[0]; bfr[jj * 2][1] = t4[1];
                    bfr[jj * 2 + 1][0] = t4[2]; bfr[jj * 2 + 1][1] = t4[3];
                }
                #pragma unroll
                for (int j = 0; j < 8; j++) mma_bf16(Cs[h2 * 8 + j], qah[k], bfr[j]);
            }
        }

        // ---- softmax (no max; clamp) + row sums ----
        #pragma unroll
        for (int j = 0; j < 16; j++) {
            #pragma unroll
            for (int e = 0; e < 4; e++)
                Cs[j][e] = __expf(fminf(Cs[j][e], 80.f));
            rs0 += Cs[j][0] + Cs[j][1];
            rs1 += Cs[j][2] + Cs[j][3];
        }

        // ---- O += P*V, single-pass bf16 ----
        #pragma unroll
        for (int kk = 0; kk < 8; kk++) {
            uint32_t pah[4];
            pah[0] = pack_bf16x2(Cs[2 * kk][0], Cs[2 * kk][1]);
            pah[1] = pack_bf16x2(Cs[2 * kk][2], Cs[2 * kk][3]);
            pah[2] = pack_bf16x2(Cs[2 * kk + 1][0], Cs[2 * kk + 1][1]);
            pah[3] = pack_bf16x2(Cs[2 * kk + 1][2], Cs[2 * kk + 1][3]);
            uint32_t vb[8][2];
            #pragma unroll
            for (int jj = 0; jj < 4; jj++) {
                uint32_t t4[4];
                ldsm_x4(t4, sb + VH_OFF + (jj * 16 + brow) * 272 + kk * 32 + bcolb);
                vb[jj * 2][0] = t4[0]; vb[jj * 2][1] = t4[1];
                vb[jj * 2 + 1][0] = t4[2]; vb[jj * 2 + 1][1] = t4[3];
            }
            #pragma unroll
            for (int j = 0; j < 8; j++) mma_bf16(Ot[j], pah, vb[j]);
        }
    }

    // row-sum reduction across the 4 lanes sharing a row
    rs0 += __shfl_xor_sync(0xffffffffu, rs0, 1);
    rs0 += __shfl_xor_sync(0xffffffffu, rs0, 2);
    rs1 += __shfl_xor_sync(0xffffffffu, rs1, 1);
    rs1 += __shfl_xor_sync(0xffffffffu, rs1, 2);
    const float i0 = 1.0f / rs0, i1 = 1.0f / rs1;

    // stage O into smem [64 d][132 n] (reuses K region), then coalesced store
    __syncthreads();
    float* ost = (float*)(smem + KH_OFF);
    {
        const int dq = (lane & 3) * 2;
        const int nq = w * 16 + (lane >> 2);
        #pragma unroll
        for (int j = 0; j < 8; j++) {
            const int d = j * 8 + dq;
            ost[d * 132 + nq]           = Ot[j][0] * i0;
            ost[(d + 1) * 132 + nq]     = Ot[j][1] * i0;
            ost[d * 132 + nq + 8]       = Ot[j][2] * i1;
            ost[(d + 1) * 132 + nq + 8] = Ot[j][3] * i1;
        }
    }
    __syncthreads();
    float* op = g_o + (size_t)b * ND * NN;
    #pragma unroll
    for (int it = 0; it < 8; it++) {
        const int i = tid + it * 256;      // 0..2047
        const int d = i >> 5, nn = (i & 31) * 4;
        *(float4*)(op + (size_t)d * NN + r0 + nn) = *(const float4*)(ost + d * 132 + nn);
    }
}

// ---------------------------------------------------------------------------
// Kernel 4: out[b][c][n] = gamma*( (Wv o)/sigma + bv ) + x.
// ---------------------------------------------------------------------------
__global__ __launch_bounds__(256) void outproj_kernel(
    const float* __restrict__ x, const float* __restrict__ Wv,
    const float* __restrict__ bv, const float* __restrict__ gamma,
    float* __restrict__ out) {
    extern __shared__ float sm[];
    float* o_s = sm;             // [64 k][128 n]
    float* W_s = sm + 64 * 128;  // [64 c][68]

    const int b = blockIdx.z;
    const int c0 = blockIdx.y * 64;
    const int n0 = blockIdx.x * 128;
    const int tid = threadIdx.x;
    const int ty = tid >> 4, tx = tid & 15;

    #pragma unroll
    for (int it = 0; it < 8; it++) {
        const int i = tid + it * 256;
        const int k = i >> 5, nn = (i & 31) << 2;
        *(float4*)(o_s + k * 128 + nn) =
            *(const float4*)(g_o + (size_t)b * ND * NN + (size_t)k * NN + n0 + nn);
    }
    #pragma unroll
    for (int it = 0; it < 4; it++) {
        const int i = tid + it * 256;
        const int c = i >> 4, kk = (i & 15) << 2;
        *(float4*)(W_s + c * 68 + kk) = *(const float4*)(Wv + (size_t)(c0 + c) * 64 + kk);
    }
    __syncthreads();

    float acc[4][8];
    #pragma unroll
    for (int i = 0; i < 4; i++)
        #pragma unroll
        for (int j = 0; j < 8; j++) acc[i][j] = 0.f;

    #pragma unroll 4
    for (int k = 0; k < 64; k++) {
        float wv[4];
        #pragma unroll
        for (int i = 0; i < 4; i++) wv[i] = W_s[(ty * 4 + i) * 68 + k];
        const float4 oa = *(const float4*)(o_s + k * 128 + tx * 8);
        const float4 ob = *(const float4*)(o_s + k * 128 + tx * 8 + 4);
        const float ov[8] = {oa.x, oa.y, oa.z, oa.w, ob.x, ob.y, ob.z, ob.w};
        #pragma unroll
        for (int i = 0; i < 4; i++)
            #pragma unroll
            for (int j = 0; j < 8; j++) acc[i][j] = fmaf(wv[i], ov[j], acc[i][j]);
    }

    const float inv = g_invsig[3];
    const float gm = gamma[0];
    #pragma unroll
    for (int i = 0; i < 4; i++) {
        const int c = c0 + ty * 4 + i;
        const float bb = bv[c];
        const size_t base = (size_t)b * NC * NN + (size_t)c * NN + n0 + tx * 8;
        const float4 xa = *(const float4*)(x + base);
        const float4 xb = *(const float4*)(x + base + 4);
        float4 r1, r2;
        r1.x = fmaf(gm, fmaf(acc[i][0], inv, bb), xa.x);
        r1.y = fmaf(gm, fmaf(acc[i][1], inv, bb), xa.y);
        r1.z = fmaf(gm, fmaf(acc[i][2], inv, bb), xa.z);
        r1.w = fmaf(gm, fmaf(acc[i][3], inv, bb), xa.w);
        r2.x = fmaf(gm, fmaf(acc[i][4], inv, bb), xb.x);
        r2.y = fmaf(gm, fmaf(acc[i][5], inv, bb), xb.y);
        r2.z = fmaf(gm, fmaf(acc[i][6], inv, bb), xb.z);
        r2.w = fmaf(gm, fmaf(acc[i][7], inv, bb), xb.w);
        *(float4*)(out + base) = r1;
        *(float4*)(out + base + 4) = r2;
    }
}

extern "C" void kernel_launch(void* const* d_in, const int* in_sizes, int n_in,
                              void* d_out, int out_size) {
    const float* x  = (const float*)d_in[0];
    const float* Wf = (const float*)d_in[1];
    const float* bf = (const float*)d_in[2];
    const float* Wg = (const float*)d_in[3];
    const float* bg = (const float*)d_in[4];
    const float* Wh = (const float*)d_in[5];
    const float* bh = (const float*)d_in[6];
    const float* Wv = (const float*)d_in[7];
    const float* bv = (const float*)d_in[8];
    const float* uf = (const float*)d_in[9];
    const float* ug = (const float*)d_in[10];
    const float* uh = (const float*)d_in[11];
    const float* uv = (const float*)d_in[12];
    const float* gamma = (const float*)d_in[13];
    float* out = (float*)d_out;

    const int PROJF_SMEM = (64 * 128 + 3 * 64 * 68) * (int)sizeof(float);  // 84992
    const int OUTP_SMEM  = (64 * 128 + 64 * 68) * (int)sizeof(float);      // 50176

    cudaFuncSetAttribute(proj_fused_kernel, cudaFuncAttributeMaxDynamicSharedMemorySize, PROJF_SMEM);
    cudaFuncSetAttribute(attn_kernel, cudaFuncAttributeMaxDynamicSharedMemorySize, ATTN_SMEM);
    cudaFuncSetAttribute(outproj_kernel, cudaFuncAttributeMaxDynamicSharedMemorySize, OUTP_SMEM);

    sigma_kernel<<<4, 512>>>(Wf, Wg, Wh, Wv, uf, ug, uh, uv);

    dim3 pg(NN / 128, NB);
    proj_fused_kernel<<<pg, 256, PROJF_SMEM>>>(x, Wf, bf, Wg, bg, Wh, bh);

    dim3 ag(NN / 128, NB);
    attn_kernel<<<ag, 256, ATTN_SMEM>>>();

    dim3 og(NN / 128, NC / 64, NB);
    outproj_kernel<<<og, 256, OUTP_SMEM>>>(x, Wv, bv, gamma, out);
}

// round 16
// speedup vs baseline: 2.5608x; 1.0530x over previous
#include <cuda_runtime.h>
#include <cuda_bf16.h>
#include <cstdint>

#define NB 4
#define NC 512
#define ND 64
#define NN 4096

// ---------------- device scratch (allocation-free rule) ----------------
__device__ float g_o[NB * ND * NN];
__device__ float g_invsig[4];
__device__ __nv_bfloat16 g_fh[NB * NN * ND];  // f [b][n][d] hi
__device__ __nv_bfloat16 g_fl[NB * NN * ND];  // f lo
__device__ __nv_bfloat16 g_gh[NB * NN * ND];  // g [b][n][d] hi
__device__ __nv_bfloat16 g_gl[NB * NN * ND];  // g lo
__device__ __nv_bfloat16 g_hh[NB * ND * NN];  // h [b][d][n] (single bf16: PV is 1-pass)

__device__ __forceinline__ uint32_t smem_to_u32(const void* p) {
    uint32_t a;
    asm("{ .reg .u64 t; cvta.to.shared.u64 t, %1; cvt.u32.u64 %0, t; }" : "=r"(a) : "l"(p));
    return a;
}
__device__ __forceinline__ uint32_t pack_bf16x2(float lo, float hi) {
    uint32_t r;
    asm("cvt.rn.bf16x2.f32 %0, %1, %2;" : "=r"(r) : "f"(hi), "f"(lo));
    return r;
}
__device__ __forceinline__ void ldsm_x4(uint32_t* r, uint32_t addr) {
    asm volatile("ldmatrix.sync.aligned.m8n8.x4.shared.b16 {%0,%1,%2,%3}, [%4];"
                 : "=r"(r[0]), "=r"(r[1]), "=r"(r[2]), "=r"(r[3]) : "r"(addr));
}
__device__ __forceinline__ void mma_bf16(float* c, const uint32_t* a, const uint32_t* b) {
    asm volatile(
        "mma.sync.aligned.m16n8k16.row.col.f32.bf16.bf16.f32 "
        "{%0,%1,%2,%3}, {%4,%5,%6,%7}, {%8,%9}, {%0,%1,%2,%3};"
        : "+f"(c[0]), "+f"(c[1]), "+f"(c[2]), "+f"(c[3])
        : "r"(a[0]), "r"(a[1]), "r"(a[2]), "r"(a[3]), "r"(b[0]), "r"(b[1]));
}
__device__ __forceinline__ void cp_async16(uint32_t smem_addr, const void* gptr) {
    asm volatile("cp.async.cg.shared.global [%0], [%1], 16;"
                 :: "r"(smem_addr), "l"(gptr) : "memory");
}
#define CP_COMMIT() asm volatile("cp.async.commit_group;" ::: "memory")
#define CP_WAIT(n)  asm volatile("cp.async.wait_group %0;" :: "n"(n) : "memory")

// ---------------------------------------------------------------------------
// Kernel 1: spectral sigma. sigma = ||W @ normalize(W^T u)||; store 1/sigma.
// ---------------------------------------------------------------------------
__global__ void sigma_kernel(const float* __restrict__ Wf, const float* __restrict__ Wg,
                             const float* __restrict__ Wh, const float* __restrict__ Wv,
                             const float* __restrict__ uf, const float* __restrict__ ug,
                             const float* __restrict__ uh, const float* __restrict__ uv) {
    __shared__ float sm_u[512];
    __shared__ float sm_v[512];
    __shared__ float sm_red[512];
    const int m = blockIdx.x;
    const int tid = threadIdx.x;
    const float* W;
    const float* u;
    int R, Ccol;
    if (m == 0)      { W = Wf; u = uf; R = 64;  Ccol = 512; }
    else if (m == 1) { W = Wg; u = ug; R = 64;  Ccol = 512; }
    else if (m == 2) { W = Wh; u = uh; R = 64;  Ccol = 512; }
    else             { W = Wv; u = uv; R = 512; Ccol = 64;  }

    if (tid < R) sm_u[tid] = u[tid];
    __syncthreads();

    if (m < 3) {
        float t = 0.f;
        #pragma unroll 8
        for (int r = 0; r < 64; r++) t += W[r * 512 + tid] * sm_u[r];
        sm_v[tid] = t;
    } else {
        const int c = tid & 63, part = tid >> 6;
        float p = 0.f;
        for (int r = part * 64; r < part * 64 + 64; r++) p += W[r * 64 + c] * sm_u[r];
        sm_red[tid] = p;
        __syncthreads();
        if (tid < 64) {
            float s = 0.f;
            #pragma unroll
            for (int q = 0; q < 8; q++) s += sm_red[q * 64 + tid];
            sm_v[tid] = s;
        }
        __syncthreads();
    }

    float val = (tid < Ccol) ? sm_v[tid] * sm_v[tid] : 0.f;
    sm_red[tid] = val;
    __syncthreads();
    for (int s = 256; s > 0; s >>= 1) {
        if (tid < s) sm_red[tid] += sm_red[tid + s];
        __syncthreads();
    }
    const float inv = rsqrtf(fmaxf(sm_red[0], 1e-24f));
    __syncthreads();

    float partial = 0.f;
    if (m < 3) {
        const int w = tid >> 5, lane = tid & 31;
        float ssq = 0.f;
        #pragma unroll
        for (int rr = 0; rr < 4; rr++) {
            const int r = w * 4 + rr;
            float acc = 0.f;
            for (int c = lane; c < 512; c += 32) acc += W[r * 512 + c] * sm_v[c];
            #pragma unroll
            for (int o = 16; o; o >>= 1) acc += __shfl_xor_sync(0xffffffffu, acc, o);
            acc *= inv;
            ssq += acc * acc;
        }
        partial = (lane == 0) ? ssq : 0.f;
    } else {
        float acc = 0.f;
        #pragma unroll 8
        for (int c = 0; c < 64; c++) acc += W[tid * 64 + c] * sm_v[c];
        acc *= inv;
        partial = acc * acc;
    }
    sm_red[tid] = partial;
    __syncthreads();
    for (int s = 256; s > 0; s >>= 1) {
        if (tid < s) sm_red[tid] += sm_red[tid + s];
        __syncthreads();
    }
    if (tid == 0) g_invsig[m] = rsqrtf(fmaxf(sm_red[0], 1e-24f));
}

// ---------------------------------------------------------------------------
// Kernel 2: FUSED QKV projection -> bf16. Loads each x tile ONCE for f,g,h.
// f,g: hi/lo pairs at [b][n][64]. h: single bf16 at [b][64][n].
// grid (NN/128, NB), 256 threads (16x16), per-thread 3 x (4k x 8n).
// dyn smem: x_s[64][128] + W_s[3][64][68]  (84992 B)
// ---------------------------------------------------------------------------
__global__ __launch_bounds__(256) void proj_fused_kernel(
    const float* __restrict__ x,
    const float* __restrict__ Wf, const float* __restrict__ bf,
    const float* __restrict__ Wg, const float* __restrict__ bg,
    const float* __restrict__ Wh, const float* __restrict__ bh) {
    extern __shared__ float sm[];
    float* x_s = sm;             // [64][128]
    float* W_s = sm + 64 * 128;  // [3][64][68]

    const int b = blockIdx.y;
    const int n0 = blockIdx.x * 128;
    const int tid = threadIdx.x;
    const int ty = tid >> 4, tx = tid & 15;
    const float* Wp[3] = {Wf, Wg, Wh};

    float acc[3][4][8];
    #pragma unroll
    for (int m = 0; m < 3; m++)
        #pragma unroll
        for (int i = 0; i < 4; i++)
            #pragma unroll
            for (int j = 0; j < 8; j++) acc[m][i][j] = 0.f;

    for (int c0 = 0; c0 < NC; c0 += 64) {
        __syncthreads();
        #pragma unroll
        for (int it = 0; it < 8; it++) {  // x_s: 2048 float4
            const int i = tid + it * 256;
            const int cc = i >> 5, nn = (i & 31) << 2;
            *(float4*)(x_s + cc * 128 + nn) =
                *(const float4*)(x + (size_t)b * NC * NN + (size_t)(c0 + cc) * NN + n0 + nn);
        }
        #pragma unroll
        for (int it = 0; it < 12; it++) {  // W_s: 3 x 1024 float4
            const int i = tid + it * 256;
            const int m = i >> 10, r = i & 1023;
            const int k = r >> 4, cc = (r & 15) << 2;
            *(float4*)(W_s + m * 64 * 68 + k * 68 + cc) =
                *(const float4*)(Wp[m] + k * 512 + c0 + cc);
        }
        __syncthreads();

        #pragma unroll 2
        for (int cc = 0; cc < 64; cc++) {
            const float4 xa = *(const float4*)(x_s + cc * 128 + tx * 8);
            const float4 xb = *(const float4*)(x_s + cc * 128 + tx * 8 + 4);
            const float xv[8] = {xa.x, xa.y, xa.z, xa.w, xb.x, xb.y, xb.z, xb.w};
            #pragma unroll
            for (int m = 0; m < 3; m++) {
                float wv[4];
                #pragma unroll
                for (int i = 0; i < 4; i++)
                    wv[i] = W_s[m * 64 * 68 + (ty * 4 + i) * 68 + cc];
                #pragma unroll
                for (int i = 0; i < 4; i++)
                    #pragma unroll
                    for (int j = 0; j < 8; j++)
                        acc[m][i][j] = fmaf(wv[i], xv[j], acc[m][i][j]);
            }
        }
    }

    // f, g: hi/lo bf16 at [b][n][64]
    #pragma unroll
    for (int m = 0; m < 2; m++) {
        const float inv = g_invsig[m];
        const float* bvec = (m == 0) ? bf : bg;
        __nv_bfloat16* oh = (m == 0) ? g_fh : g_gh;
        __nv_bfloat16* ol = (m == 0) ? g_fl : g_gl;
        float v[4][8];
        #pragma unroll
        for (int i = 0; i < 4; i++) {
            const float bb = bvec[ty * 4 + i];
            #pragma unroll
            for (int j = 0; j < 8; j++) v[i][j] = fmaf(acc[m][i][j], inv, bb);
        }
        #pragma unroll
        for (int j = 0; j < 8; j++) {
            const int n = n0 + tx * 8 + j;
            const size_t base = ((size_t)b * NN + n) * 64 + ty * 4;
            uint32_t h0 = pack_bf16x2(v[0][j], v[1][j]);
            uint32_t h1 = pack_bf16x2(v[2][j], v[3][j]);
            float c0f = __uint_as_float(h0 << 16), c1f = __uint_as_float(h0 & 0xffff0000u);
            float c2f = __uint_as_float(h1 << 16), c3f = __uint_as_float(h1 & 0xffff0000u);
            uint32_t l0 = pack_bf16x2(v[0][j] - c0f, v[1][j] - c1f);
            uint32_t l1 = pack_bf16x2(v[2][j] - c2f, v[3][j] - c3f);
            *(uint2*)(oh + base) = make_uint2(h0, h1);
            *(uint2*)(ol + base) = make_uint2(l0, l1);
        }
    }
    // h: single bf16 at [b][64][n]
    {
        const float inv = g_invsig[2];
        #pragma unroll
        for (int i = 0; i < 4; i++) {
            const int k = ty * 4 + i;
            const float bb = bh[k];
            const size_t base = ((size_t)b * ND + k) * NN + n0 + tx * 8;
            uint32_t hw[4];
            #pragma unroll
            for (int q = 0; q < 4; q++)
                hw[q] = pack_bf16x2(fmaf(acc[2][i][2 * q], inv, bb),
                                    fmaf(acc[2][i][2 * q + 1], inv, bb));
            *(uint4*)(g_hh + base) = make_uint4(hw[0], hw[1], hw[2], hw[3]);
        }
    }
}

// ---------------------------------------------------------------------------
// Kernel 3: flash attention, mma.sync. S: bf16 hi/lo 3-pass. PV: 1-pass bf16.
// K/V tiles double-buffered via cp.async (prefetch i+1 during compute i).
// grid (NN/128, NB), 256 threads = 8 warps; warp w owns q rows w*16..w*16+15.
// smem: QH 18432 | QL 18432 | 2 x (KH 18432 + KL 18432 + V 17408) = 145408 B
// ---------------------------------------------------------------------------
#define QH_OFF 0
#define QL_OFF 18432
#define KV_OFF 36864
#define KV_BUF 54272
#define ATTN_SMEM (KV_OFF + 2 * KV_BUF)   // 145408

__global__ __launch_bounds__(256, 1) void attn_kernel() {
    extern __shared__ char smem[];
    const uint32_t sb = smem_to_u32(smem);
    const int b = blockIdx.y;
    const int r0 = blockIdx.x * 128;
    const int tid = threadIdx.x;
    const int w = tid >> 5, lane = tid & 31;

    const __nv_bfloat16* __restrict__ fh = g_fh + (size_t)b * NN * ND;
    const __nv_bfloat16* __restrict__ fl = g_fl + (size_t)b * NN * ND;
    const __nv_bfloat16* __restrict__ gh = g_gh + (size_t)b * NN * ND;
    const __nv_bfloat16* __restrict__ gl = g_gl + (size_t)b * NN * ND;
    const __nv_bfloat16* __restrict__ hh = g_hh + (size_t)b * ND * NN;

    // Q tiles -> smem
    #pragma unroll
    for (int it = 0; it < 4; it++) {
        const int idx = tid + it * 256;
        const int row = idx >> 3, ch = idx & 7;
        *(uint4*)(smem + QH_OFF + row * 144 + ch * 16) =
            *(const uint4*)(fh + (size_t)(r0 + row) * 64 + ch * 8);
        *(uint4*)(smem + QL_OFF + row * 144 + ch * 16) =
            *(const uint4*)(fl + (size_t)(r0 + row) * 64 + ch * 8);
    }
    __syncthreads();

    // Q A-fragments (m16k16), kept in registers for all 32 tiles
    const int arow = (lane & 7) + ((lane >> 3) & 1) * 8;
    const int acolb = ((lane >> 4) & 1) * 16;
    uint32_t qah[4][4], qal[4][4];
    #pragma unroll
    for (int k = 0; k < 4; k++) {
        ldsm_x4(qah[k], sb + QH_OFF + (w * 16 + arow) * 144 + k * 32 + acolb);
        ldsm_x4(qal[k], sb + QL_OFF + (w * 16 + arow) * 144 + k * 32 + acolb);
    }

    const int brow = (lane & 7) + ((lane >> 4) & 1) * 8;
    const int bcolb = ((lane >> 3) & 1) * 16;

    float Ot[8][4];
    #pragma unroll
    for (int j = 0; j < 8; j++)
        #pragma unroll
        for (int e = 0; e < 4; e++) Ot[j][e] = 0.f;
    float rs0 = 0.f, rs1 = 0.f;

    // ---- prefetch tile 0 into buffer 0 ----
    {
        const uint32_t kb = sb + KV_OFF;
        #pragma unroll
        for (int it = 0; it < 4; it++) {
            const int idx = tid + it * 256;
            const int row = idx >> 3, ch = idx & 7;
            cp_async16(kb + row * 144 + ch * 16, gh + (size_t)row * 64 + ch * 8);
            cp_async16(kb + 18432 + row * 144 + ch * 16, gl + (size_t)row * 64 + ch * 8);
        }
        #pragma unroll
        for (int it = 0; it < 4; it++) {
            const int idx = tid + it * 256;
            const int row = idx >> 4, ch = idx & 15;
            cp_async16(kb + 36864 + row * 272 + ch * 16, hh + (size_t)row * NN + ch * 8);
        }
        CP_COMMIT();
    }

    for (int iter = 0; iter < NN / 128; iter++) {
        const uint32_t kb = sb + KV_OFF + (iter & 1) * KV_BUF;

        if (iter + 1 < NN / 128) {
            // prefetch tile iter+1 into the other buffer
            const int c1 = (iter + 1) * 128;
            const uint32_t nb = sb + KV_OFF + ((iter + 1) & 1) * KV_BUF;
            #pragma unroll
            for (int it = 0; it < 4; it++) {
                const int idx = tid + it * 256;
                const int row = idx >> 3, ch = idx & 7;
                cp_async16(nb + row * 144 + ch * 16, gh + (size_t)(c1 + row) * 64 + ch * 8);
                cp_async16(nb + 18432 + row * 144 + ch * 16, gl + (size_t)(c1 + row) * 64 + ch * 8);
            }
            #pragma unroll
            for (int it = 0; it < 4; it++) {
                const int idx = tid + it * 256;
                const int row = idx >> 4, ch = idx & 15;
                cp_async16(nb + 36864 + row * 272 + ch * 16, hh + (size_t)row * NN + c1 + ch * 8);
            }
            CP_COMMIT();
            CP_WAIT(1);   // tile `iter` complete
        } else {
            CP_WAIT(0);
        }
        __syncthreads();

        // ---- S = Qh*Kh + Ql*Kh + Qh*Kl ----
        float Cs[16][4];
        #pragma unroll
        for (int j = 0; j < 16; j++)
            #pragma unroll
            for (int e = 0; e < 4; e++) Cs[j][e] = 0.f;

        #pragma unroll
        for (int k = 0; k < 4; k++) {
            #pragma unroll
            for (int h2 = 0; h2 < 2; h2++) {
                uint32_t bfr[8][2];
                #pragma unroll
                for (int jj = 0; jj < 4; jj++) {
                    uint32_t t4[4];
                    ldsm_x4(t4, kb + ((h2 * 8 + jj * 2) * 8 + brow) * 144 + k * 32 + bcolb);
                    bfr[jj * 2][0] = t4[0]; bfr[jj * 2][1] = t4[1];
                    bfr[jj * 2 + 1][0] = t4[2]; bfr[jj * 2 + 1][1] = t4[3];
                }
                #pragma unroll
                for (int j = 0; j < 8; j++) mma_bf16(Cs[h2 * 8 + j], qah[k], bfr[j]);
                #pragma unroll
                for (int j = 0; j < 8; j++) mma_bf16(Cs[h2 * 8 + j], qal[k], bfr[j]);
                #pragma unroll
                for (int jj = 0; jj < 4; jj++) {
                    uint32_t t4[4];
                    ldsm_x4(t4, kb + 18432 + ((h2 * 8 + jj * 2) * 8 + brow) * 144 + k * 32 + bcolb);
                    bfr[jj * 2][0] = t4[0]; bfr[jj * 2][1] = t4[1];
                    bfr[jj * 2 + 1][0] = t4[2]; bfr[jj * 2 + 1][1] = t4[3];
                }
                #pragma unroll
                for (int j = 0; j < 8; j++) mma_bf16(Cs[h2 * 8 + j], qah[k], bfr[j]);
            }
        }

        // ---- softmax (no max; clamp) + row sums ----
        #pragma unroll
        for (int j = 0; j < 16; j++) {
            #pragma unroll
            for (int e = 0; e < 4; e++)
                Cs[j][e] = __expf(fminf(Cs[j][e], 80.f));
            rs0 += Cs[j][0] + Cs[j][1];
            rs1 += Cs[j][2] + Cs[j][3];
        }

        // ---- O += P*V, single-pass bf16 ----
        #pragma unroll
        for (int kk = 0; kk < 8; kk++) {
            uint32_t pah[4];
            pah[0] = pack_bf16x2(Cs[2 * kk][0], Cs[2 * kk][1]);
            pah[1] = pack_bf16x2(Cs[2 * kk][2], Cs[2 * kk][3]);
            pah[2] = pack_bf16x2(Cs[2 * kk + 1][0], Cs[2 * kk + 1][1]);
            pah[3] = pack_bf16x2(Cs[2 * kk + 1][2], Cs[2 * kk + 1][3]);
            uint32_t vb[8][2];
            #pragma unroll
            for (int jj = 0; jj < 4; jj++) {
                uint32_t t4[4];
                ldsm_x4(t4, kb + 36864 + (jj * 16 + brow) * 272 + kk * 32 + bcolb);
                vb[jj * 2][0] = t4[0]; vb[jj * 2][1] = t4[1];
                vb[jj * 2 + 1][0] = t4[2]; vb[jj * 2 + 1][1] = t4[3];
            }
            #pragma unroll
            for (int j = 0; j < 8; j++) mma_bf16(Ot[j], pah, vb[j]);
        }
        __syncthreads();  // compute done before this buffer is overwritten
    }

    // row-sum reduction across the 4 lanes sharing a row
    rs0 += __shfl_xor_sync(0xffffffffu, rs0, 1);
    rs0 += __shfl_xor_sync(0xffffffffu, rs0, 2);
    rs1 += __shfl_xor_sync(0xffffffffu, rs1, 1);
    rs1 += __shfl_xor_sync(0xffffffffu, rs1, 2);
    const float i0 = 1.0f / rs0, i1 = 1.0f / rs1;

    // stage O into smem [64 d][132 n] (reuses KV buffer 0), coalesced store
    __syncthreads();
    float* ost = (float*)(smem + KV_OFF);
    {
        const int dq = (lane & 3) * 2;
        const int nq = w * 16 + (lane >> 2);
        #pragma unroll
        for (int j = 0; j < 8; j++) {
            const int d = j * 8 + dq;
            ost[d * 132 + nq]           = Ot[j][0] * i0;
            ost[(d + 1) * 132 + nq]     = Ot[j][1] * i0;
            ost[d * 132 + nq + 8]       = Ot[j][2] * i1;
            ost[(d + 1) * 132 + nq + 8] = Ot[j][3] * i1;
        }
    }
    __syncthreads();
    float* op = g_o + (size_t)b * ND * NN;
    #pragma unroll
    for (int it = 0; it < 8; it++) {
        const int i = tid + it * 256;      // 0..2047
        const int d = i >> 5, nn = (i & 31) * 4;
        *(float4*)(op + (size_t)d * NN + r0 + nn) = *(const float4*)(ost + d * 132 + nn);
    }
}

// ---------------------------------------------------------------------------
// Kernel 4: out[b][c][n] = gamma*( (Wv o)/sigma + bv ) + x.
// ---------------------------------------------------------------------------
__global__ __launch_bounds__(256) void outproj_kernel(
    const float* __restrict__ x, const float* __restrict__ Wv,
    const float* __restrict__ bv, const float* __restrict__ gamma,
    float* __restrict__ out) {
    extern __shared__ float sm[];
    float* o_s = sm;             // [64 k][128 n]
    float* W_s = sm + 64 * 128;  // [64 c][68]

    const int b = blockIdx.z;
    const int c0 = blockIdx.y * 64;
    const int n0 = blockIdx.x * 128;
    const int tid = threadIdx.x;
    const int ty = tid >> 4, tx = tid & 15;

    #pragma unroll
    for (int it = 0; it < 8; it++) {
        const int i = tid + it * 256;
        const int k = i >> 5, nn = (i & 31) << 2;
        *(float4*)(o_s + k * 128 + nn) =
            *(const float4*)(g_o + (size_t)b * ND * NN + (size_t)k * NN + n0 + nn);
    }
    #pragma unroll
    for (int it = 0; it < 4; it++) {
        const int i = tid + it * 256;
        const int c = i >> 4, kk = (i & 15) << 2;
        *(float4*)(W_s + c * 68 + kk) = *(const float4*)(Wv + (size_t)(c0 + c) * 64 + kk);
    }
    __syncthreads();

    float acc[4][8];
    #pragma unroll
    for (int i = 0; i < 4; i++)
        #pragma unroll
        for (int j = 0; j < 8; j++) acc[i][j] = 0.f;

    #pragma unroll 4
    for (int k = 0; k < 64; k++) {
        float wv[4];
        #pragma unroll
        for (int i = 0; i < 4; i++) wv[i] = W_s[(ty * 4 + i) * 68 + k];
        const float4 oa = *(const float4*)(o_s + k * 128 + tx * 8);
        const float4 ob = *(const float4*)(o_s + k * 128 + tx * 8 + 4);
        const float ov[8] = {oa.x, oa.y, oa.z, oa.w, ob.x, ob.y, ob.z, ob.w};
        #pragma unroll
        for (int i = 0; i < 4; i++)
            #pragma unroll
            for (int j = 0; j < 8; j++) acc[i][j] = fmaf(wv[i], ov[j], acc[i][j]);
    }

    const float inv = g_invsig[3];
    const float gm = gamma[0];
    #pragma unroll
    for (int i = 0; i < 4; i++) {
        const int c = c0 + ty * 4 + i;
        const float bb = bv[c];
        const size_t base = (size_t)b * NC * NN + (size_t)c * NN + n0 + tx * 8;
        const float4 xa = *(const float4*)(x + base);
        const float4 xb = *(const float4*)(x + base + 4);
        float4 r1, r2;
        r1.x = fmaf(gm, fmaf(acc[i][0], inv, bb), xa.x);
        r1.y = fmaf(gm, fmaf(acc[i][1], inv, bb), xa.y);
        r1.z = fmaf(gm, fmaf(acc[i][2], inv, bb), xa.z);
        r1.w = fmaf(gm, fmaf(acc[i][3], inv, bb), xa.w);
        r2.x = fmaf(gm, fmaf(acc[i][4], inv, bb), xb.x);
        r2.y = fmaf(gm, fmaf(acc[i][5], inv, bb), xb.y);
        r2.z = fmaf(gm, fmaf(acc[i][6], inv, bb), xb.z);
        r2.w = fmaf(gm, fmaf(acc[i][7], inv, bb), xb.w);
        *(float4*)(out + base) = r1;
        *(float4*)(out + base + 4) = r2;
    }
}

extern "C" void kernel_launch(void* const* d_in, const int* in_sizes, int n_in,
                              void* d_out, int out_size) {
    const float* x  = (const float*)d_in[0];
    const float* Wf = (const float*)d_in[1];
    const float* bf = (const float*)d_in[2];
    const float* Wg = (const float*)d_in[3];
    const float* bg = (const float*)d_in[4];
    const float* Wh = (const float*)d_in[5];
    const float* bh = (const float*)d_in[6];
    const float* Wv = (const float*)d_in[7];
    const float* bv = (const float*)d_in[8];
    const float* uf = (const float*)d_in[9];
    const float* ug = (const float*)d_in[10];
    const float* uh = (const float*)d_in[11];
    const float* uv = (const float*)d_in[12];
    const float* gamma = (const float*)d_in[13];
    float* out = (float*)d_out;

    const int PROJF_SMEM = (64 * 128 + 3 * 64 * 68) * (int)sizeof(float);  // 84992
    const int OUTP_SMEM  = (64 * 128 + 64 * 68) * (int)sizeof(float);      // 50176

    cudaFuncSetAttribute(proj_fused_kernel, cudaFuncAttributeMaxDynamicSharedMemorySize, PROJF_SMEM);
    cudaFuncSetAttribute(attn_kernel, cudaFuncAttributeMaxDynamicSharedMemorySize, ATTN_SMEM);
    cudaFuncSetAttribute(outproj_kernel, cudaFuncAttributeMaxDynamicSharedMemorySize, OUTP_SMEM);

    sigma_kernel<<<4, 512>>>(Wf, Wg, Wh, Wv, uf, ug, uh, uv);

    dim3 pg(NN / 128, NB);
    proj_fused_kernel<<<pg, 256, PROJF_SMEM>>>(x, Wf, bf, Wg, bg, Wh, bh);

    dim3 ag(NN / 128, NB);
    attn_kernel<<<ag, 256, ATTN_SMEM>>>();

    dim3 og(NN / 128, NC / 64, NB);
    outproj_kernel<<<og, 256, OUTP_SMEM>>>(x, Wv, bv, gamma, out);
}